// round 16
// baseline (speedup 1.0000x reference)
#include <cuda_runtime.h>
#include <cstdint>

#define THRESH 1.25f

constexpr int B    = 16;
constexpr int CIN  = 8192;   // 64*64*2
constexpr int CHID = 512;
constexpr int COUT = 100;
constexpr int T    = 300;
constexpr int NW0  = CIN / 32;   // 256 words per (b,t)
constexpr int NW1  = CHID / 32;  // 16 words per (b,t)
constexpr int HW   = NW0 / 2;    // 128 words per half (layer 1)
constexpr int D    = 10;         // LIF prefetch ring depth
constexpr int NC   = 3;          // t-chunks
constexpr int CH   = T / NC;     // 100 per chunk (divisible by D)

// ---------------- scratch (static device globals; allocation-free) -------------
__device__ __align__(256) float    d_WT1[CIN * CHID];     // 16 MB  [i][o] (UNSCALED v1^T)
__device__ __align__(256) float    d_WT2[CHID * CHID];    // 1 MB   [i][o] (scaled)
__device__ __align__(256) float    d_WT3[CHID * 128];     // 256 KB [i][o pad 128] (scaled)
__device__ __align__(256) float    d_scale1[CHID];
__device__ __align__(256) unsigned d_bits0[T * B * NW0];  // input spikes [t][b][w]
__device__ __align__(256) unsigned d_bits1[T * B * NW1];  // hidden spikes [t][b][w]
__device__ __align__(256) unsigned d_bits2[T * B * NW1];
__device__ __align__(256) float    d_zpart[2][T * B * CHID]; // layer-1 i-half partials
__device__ __align__(256) float    d_z [T * B * CHID];    // layer-2 z [t][b][o]
__device__ __align__(256) float    d_z3[T * B * COUT];
__device__ __align__(256) float2   d_st1[B * CHID];       // lif1 (cur, volt) chunk state
__device__ __align__(256) float2   d_st2[B * CHID];       // lif2 state

// ---------------- prep_all: every weight-prep task in one kernel ----------------
__global__ __launch_bounds__(256) void prep_all(const float* __restrict__ v1,
                                                const float* __restrict__ g1,
                                                const float* __restrict__ v2,
                                                const float* __restrict__ g2,
                                                const float* __restrict__ v3,
                                                const float* __restrict__ g3)
{
    int blk = blockIdx.x;
    int tid = threadIdx.x, lane = tid & 31, w = tid >> 5;

    if (blk >= 592) {
        __shared__ float tile[64][65];
        int idx = blk - 592;
        int i0 = (idx & 127) * 64;
        int o0 = (idx >> 7) * 64;
        int oy = tid >> 4;
        int ix = (tid & 15) * 4;
        #pragma unroll
        for (int k = 0; k < 4; k++) {
            int ol = oy + k * 16;
            float4 val = *(const float4*)&v1[(size_t)(o0 + ol) * CIN + i0 + ix];
            tile[ix + 0][ol] = val.x;
            tile[ix + 1][ol] = val.y;
            tile[ix + 2][ol] = val.z;
            tile[ix + 3][ol] = val.w;
        }
        __syncthreads();
        int iy = tid >> 4;
        int ox = (tid & 15) * 4;
        #pragma unroll
        for (int k = 0; k < 4; k++) {
            int il = iy + k * 16;
            float4 w4;
            w4.x = tile[il][ox + 0];
            w4.y = tile[il][ox + 1];
            w4.z = tile[il][ox + 2];
            w4.w = tile[il][ox + 3];
            *(float4*)&d_WT1[(size_t)(i0 + il) * CHID + o0 + ox] = w4;
        }
        return;
    }

    if (blk >= 80) {
        __shared__ float red[8];
        int r = blk - 80;
        const float* row = v1 + (size_t)r * CIN;
        float s = 0.f;
        for (int i = tid; i < CIN; i += 256) { float x = row[i]; s = fmaf(x, x, s); }
        #pragma unroll
        for (int d = 16; d > 0; d >>= 1) s += __shfl_down_sync(0xffffffffu, s, d);
        if (lane == 0) red[w] = s;
        __syncthreads();
        if (tid == 0) {
            float tot = 0.f;
            #pragma unroll
            for (int j = 0; j < 8; j++) tot += red[j];
            d_scale1[r] = g1[r] / sqrtf(tot);
        }
        return;
    }

    const float *v, *g;
    float* wt;
    int bx, by, OSTRIDE, NOV;
    if (blk < 64) { v = v2; g = g2; wt = d_WT2; bx = blk & 7; by = blk >> 3; OSTRIDE = 512; NOV = 512; }
    else { int l = blk - 64; v = v3; g = g3; wt = d_WT3; bx = l & 7; by = l >> 3; OSTRIDE = 128; NOV = 100; }
    constexpr int NI = 512;
    int i0 = bx * 64, o0 = by * 64;

    __shared__ float sscale[64];
    __shared__ float tile[64][65];

    #pragma unroll
    for (int r = 0; r < 8; r++) {
        int o = o0 + w * 8 + r;
        float s = 0.f;
        if (o < NOV) {
            const float* row = v + (size_t)o * NI;
            #pragma unroll
            for (int k = 0; k < 16; k++) { float x = row[lane + 32 * k]; s = fmaf(x, x, s); }
        }
        #pragma unroll
        for (int d = 16; d > 0; d >>= 1) s += __shfl_down_sync(0xffffffffu, s, d);
        if (lane == 0) sscale[w * 8 + r] = (o < NOV) ? g[o] / sqrtf(s) : 0.f;
    }
    __syncthreads();

    int oy = tid >> 4;
    int ix = (tid & 15) * 4;
    #pragma unroll
    for (int k = 0; k < 4; k++) {
        int ol = oy + k * 16;
        int o  = o0 + ol;
        float4 val = make_float4(0.f, 0.f, 0.f, 0.f);
        if (o < NOV) val = *(const float4*)&v[(size_t)o * NI + i0 + ix];
        tile[ix + 0][ol] = val.x;
        tile[ix + 1][ol] = val.y;
        tile[ix + 2][ol] = val.z;
        tile[ix + 3][ol] = val.w;
    }
    __syncthreads();

    int iy = tid >> 4;
    int ox = (tid & 15) * 4;
    float4 sc;
    sc.x = sscale[ox + 0]; sc.y = sscale[ox + 1];
    sc.z = sscale[ox + 2]; sc.w = sscale[ox + 3];
    #pragma unroll
    for (int k = 0; k < 4; k++) {
        int il = iy + k * 16;
        float4 w4;
        w4.x = tile[il][ox + 0] * sc.x;
        w4.y = tile[il][ox + 1] * sc.y;
        w4.z = tile[il][ox + 2] * sc.z;
        w4.w = tile[il][ox + 3] * sc.w;
        *(float4*)&wt[(size_t)(i0 + il) * OSTRIDE + o0 + ox] = w4;
    }
}

// ---------------- bitpack (coalesced, smem byte-transpose) ----------------------
__global__ __launch_bounds__(256) void bitpack(const float* __restrict__ spike)
{
    __shared__ unsigned char sb[32 * 308];
    int blk = blockIdx.x;
    int b  = blk >> 8;
    int ig = blk & 255;
    int tid = threadIdx.x, lane = tid & 31, w = tid >> 5;

    #pragma unroll
    for (int k = 0; k < 4; k++) {
        int il = w + 8 * k;
        const float4* row4 = (const float4*)(spike + ((size_t)b * CIN + ig * 32 + il) * T);
        #pragma unroll
        for (int j = 0; j < 3; j++) {
            int f = lane + 32 * j;
            if (f < 75) {
                float4 v = row4[f];
                unsigned p = (v.x > 0.5f ? 1u : 0u)
                           | (v.y > 0.5f ? 1u : 0u) << 8
                           | (v.z > 0.5f ? 1u : 0u) << 16
                           | (v.w > 0.5f ? 1u : 0u) << 24;
                *(unsigned*)&sb[il * 308 + 4 * f] = p;
            }
        }
    }
    __syncthreads();
    for (int t = tid; t < T; t += 256) {
        unsigned m = 0;
        #pragma unroll
        for (int i = 0; i < 32; i++) m |= (unsigned)sb[i * 308 + t] << i;
        d_bits0[(size_t)t * (B * NW0) + b * NW0 + ig] = m;
    }
}

// ---------------- layer-1 sparse gather, t-chunked, i-halved, float4 x 128 -----
__global__ __launch_bounds__(128) void gather_hid1(int t0)
{
    const float4* __restrict__ wt = (const float4*)d_WT1;
    int t = t0 + blockIdx.x, b = blockIdx.y, h = blockIdx.z;
    const unsigned* bp = d_bits0 + ((size_t)t * B + b) * NW0 + h * HW;

    __shared__ unsigned short sidx[HW * 32];
    __shared__ int wcnt[4];
    int tid = threadIdx.x, lane = tid & 31, w = tid >> 5;

    int word = w * 32 + lane;
    unsigned m = bp[word];
    int c = __popc(m);
    int x = c;
    #pragma unroll
    for (int d = 1; d < 32; d <<= 1) {
        int y = __shfl_up_sync(0xffffffffu, x, d);
        if (lane >= d) x += y;
    }
    if (lane == 31) wcnt[w] = x;
    __syncthreads();
    int base = 0;
    #pragma unroll
    for (int j = 0; j < 4; j++) if (j < w) base += wcnt[j];
    int mybase = base + x - c;
    while (m) {
        int bpos = __ffs((int)m) - 1;
        m &= m - 1;
        sidx[mybase++] = (unsigned short)(word * 32 + bpos);
    }
    __syncthreads();

    int cnt = wcnt[0] + wcnt[1] + wcnt[2] + wcnt[3];
    int rowbase = h * (CIN / 2);

    float ax = 0.f, ay = 0.f, az = 0.f, aw = 0.f;
    int k = 0;
    for (; k + 8 <= cnt; k += 8) {
        float4 r[8];
        #pragma unroll
        for (int u = 0; u < 8; u++) {
            int i = rowbase + sidx[k + u];
            r[u] = wt[(size_t)i * 128 + tid];
        }
        #pragma unroll
        for (int u = 0; u < 8; u++) { ax += r[u].x; ay += r[u].y; az += r[u].z; aw += r[u].w; }
    }
    for (; k < cnt; k++) {
        int i = rowbase + sidx[k];
        float4 r0 = wt[(size_t)i * 128 + tid];
        ax += r0.x; ay += r0.y; az += r0.z; aw += r0.w;
    }
    float4 o; o.x = ax; o.y = ay; o.z = az; o.w = aw;
    ((float4*)d_zpart[h])[((size_t)t * B + b) * 128 + tid] = o;
}

// ---------------- LIF layer 1, t-chunked: z = scale1[o]*(p0+p1) ------------------
__global__ __launch_bounds__(128) void lif_hid1(const float* __restrict__ cds,
                                                const float* __restrict__ vds,
                                                int t0, int t1)
{
    int gid  = blockIdx.x * blockDim.x + threadIdx.x;  // b*512+o
    int lane = threadIdx.x & 31;
    float a  = 1.f - cds[0];
    float bb = 1.f - vds[0];
    float sc = d_scale1[gid & (CHID - 1)];

    float cur, volt;
    if (t0 == 0) { cur = 0.f; volt = 0.f; }
    else { float2 st = d_st1[gid]; cur = st.x; volt = st.y; }

    float2 zb[D];
    #pragma unroll
    for (int j = 0; j < D; j++) {
        zb[j].x = d_zpart[0][(size_t)(t0 + j) * (B * CHID) + gid];
        zb[j].y = d_zpart[1][(size_t)(t0 + j) * (B * CHID) + gid];
    }

    for (int tb = t0; tb < t1; tb += D) {
        #pragma unroll
        for (int j = 0; j < D; j++) {
            int t = tb + j;
            float2 p = zb[j];
            float zt = (p.x + p.y) * sc;
            int tp = t + D;
            if (tp < t1) {
                zb[j].x = d_zpart[0][(size_t)tp * (B * CHID) + gid];
                zb[j].y = d_zpart[1][(size_t)tp * (B * CHID) + gid];
            }
            cur  = fmaf(a, cur, zt);
            volt = fmaf(bb, volt, cur);
            bool s = volt >= THRESH;
            unsigned msk = __ballot_sync(0xffffffffu, s);
            volt = s ? 0.f : volt;
            if (lane == 0) d_bits1[(size_t)t * (B * NW1) + (gid >> 5)] = msk;
        }
    }
    if (t1 < T) { float2 st; st.x = cur; st.y = volt; d_st1[gid] = st; }
}

// ---------------- layer-2 sparse gather, t-chunked, per-t full-width ------------
__global__ __launch_bounds__(128) void gather_hid2(int t0)
{
    const float4* __restrict__ wt = (const float4*)d_WT2;
    int t = t0 + blockIdx.x, b = blockIdx.y;
    const unsigned* bp = d_bits1 + ((size_t)t * B + b) * NW1;

    __shared__ unsigned short sidx[NW1 * 32];
    __shared__ int scount;
    int tid = threadIdx.x, lane = tid & 31;

    if (tid < 32) {
        unsigned m = (lane < NW1) ? bp[lane] : 0u;
        int c = __popc(m);
        int x = c;
        #pragma unroll
        for (int d = 1; d < 32; d <<= 1) {
            int y = __shfl_up_sync(0xffffffffu, x, d);
            if (lane >= d) x += y;
        }
        int base = x - c;
        while (m) {
            int bpos = __ffs((int)m) - 1;
            m &= m - 1;
            sidx[base++] = (unsigned short)(lane * 32 + bpos);
        }
        if (lane == 31) scount = x;
    }
    __syncthreads();

    int cnt = scount;
    float ax = 0.f, ay = 0.f, az = 0.f, aw = 0.f;
    int k = 0;
    for (; k + 8 <= cnt; k += 8) {
        float4 r[8];
        #pragma unroll
        for (int u = 0; u < 8; u++) { int i = sidx[k + u]; r[u] = wt[(size_t)i * 128 + tid]; }
        #pragma unroll
        for (int u = 0; u < 8; u++) { ax += r[u].x; ay += r[u].y; az += r[u].z; aw += r[u].w; }
    }
    for (; k < cnt; k++) {
        float4 r0 = wt[(size_t)sidx[k] * 128 + tid];
        ax += r0.x; ay += r0.y; az += r0.z; aw += r0.w;
    }
    float4 o; o.x = ax; o.y = ay; o.z = az; o.w = aw;
    ((float4*)d_z)[((size_t)t * B + b) * 128 + tid] = o;
}

// ---------------- LIF layer 2, t-chunked (reads d_z) -----------------------------
__global__ __launch_bounds__(128) void lif_hid2(const float* __restrict__ cds,
                                                const float* __restrict__ vds,
                                                int t0, int t1)
{
    int gid  = blockIdx.x * blockDim.x + threadIdx.x;
    int lane = threadIdx.x & 31;
    float a  = 1.f - cds[1];
    float bb = 1.f - vds[1];

    float cur, volt;
    if (t0 == 0) { cur = 0.f; volt = 0.f; }
    else { float2 st = d_st2[gid]; cur = st.x; volt = st.y; }

    float zb[D];
    #pragma unroll
    for (int j = 0; j < D; j++) zb[j] = d_z[(size_t)(t0 + j) * (B * CHID) + gid];

    for (int tb = t0; tb < t1; tb += D) {
        #pragma unroll
        for (int j = 0; j < D; j++) {
            int t = tb + j;
            float zt = zb[j];
            int tp = t + D;
            if (tp < t1) zb[j] = d_z[(size_t)tp * (B * CHID) + gid];
            cur  = fmaf(a, cur, zt);
            volt = fmaf(bb, volt, cur);
            bool s = volt >= THRESH;
            unsigned msk = __ballot_sync(0xffffffffu, s);
            volt = s ? 0.f : volt;
            if (lane == 0) d_bits2[(size_t)t * (B * NW1) + (gid >> 5)] = msk;
        }
    }
    if (t1 < T) { float2 st; st.x = cur; st.y = volt; d_st2[gid] = st; }
}

// ---------------- layer-3 gather, t-chunked --------------------------------------
__global__ void gather_out(int t0)
{
    int t = t0 + blockIdx.x, b = blockIdx.y;
    const unsigned* bp = d_bits2 + ((size_t)t * B + b) * NW1;

    __shared__ unsigned short sidx[NW1 * 32];
    __shared__ int scount;
    int tid = threadIdx.x, lane = tid & 31;

    if (tid < 32) {
        unsigned m = (lane < NW1) ? bp[lane] : 0u;
        int c = __popc(m);
        int x = c;
        #pragma unroll
        for (int d = 1; d < 32; d <<= 1) {
            int y = __shfl_up_sync(0xffffffffu, x, d);
            if (lane >= d) x += y;
        }
        int base = x - c;
        while (m) {
            int bpos = __ffs((int)m) - 1;
            m &= m - 1;
            sidx[base++] = (unsigned short)(lane * 32 + bpos);
        }
        if (lane == 31) scount = x;
    }
    __syncthreads();

    int cnt = scount;
    float acc = 0.f;
    int k = 0;
    for (; k + 8 <= cnt; k += 8) {
        float r[8];
        #pragma unroll
        for (int u = 0; u < 8; u++) { int i = sidx[k + u]; r[u] = d_WT3[i * 128 + tid]; }
        #pragma unroll
        for (int u = 0; u < 8; u++) acc += r[u];
    }
    for (; k < cnt; k++) acc += d_WT3[sidx[k] * 128 + tid];

    if (tid < COUT) d_z3[((size_t)t * B + b) * COUT + tid] = acc;
}

// ---------------- LIF output layer (full T), depth-10 static ring ----------------
__global__ __launch_bounds__(128) void lif_out(const float* __restrict__ cds,
                                               const float* __restrict__ vds,
                                               float* __restrict__ out)
{
    int gid = blockIdx.x * blockDim.x + threadIdx.x;
    if (gid >= B * COUT) return;
    int b = gid / COUT, c = gid % COUT;
    float a  = 1.f - cds[2];
    float bb = 1.f - vds[2];
    float cur = 0.f, volt = 0.f;
    float* orow = out + ((size_t)b * COUT + c) * T;

    float zb[D];
    #pragma unroll
    for (int j = 0; j < D; j++) zb[j] = d_z3[(size_t)j * (B * COUT) + gid];

    for (int tb = 0; tb < T; tb += D) {
        #pragma unroll
        for (int j = 0; j < D; j++) {
            int t = tb + j;
            float zt = zb[j];
            int tp = t + D;
            if (tp < T) zb[j] = d_z3[(size_t)tp * (B * COUT) + gid];
            cur  = fmaf(a, cur, zt);
            volt = fmaf(bb, volt, cur);
            bool s = volt >= THRESH;
            volt = s ? 0.f : volt;
            orow[t] = s ? 1.0f : 0.0f;
        }
    }
}

// ---------------- streams/events (context resources, not tracked device mem) ---
struct SideStreams {
    cudaStream_t s1, s2;
    cudaEvent_t  evRoot, evBits, evPrep, evEnd;
    cudaEvent_t  evG1[NC], evL1[NC], evG2[NC], evL2[NC], evG3[NC];
    SideStreams() {
        cudaStreamCreateWithFlags(&s1, cudaStreamNonBlocking);
        cudaStreamCreateWithFlags(&s2, cudaStreamNonBlocking);
        cudaEventCreateWithFlags(&evRoot, cudaEventDisableTiming);
        cudaEventCreateWithFlags(&evBits, cudaEventDisableTiming);
        cudaEventCreateWithFlags(&evPrep, cudaEventDisableTiming);
        cudaEventCreateWithFlags(&evEnd,  cudaEventDisableTiming);
        for (int c = 0; c < NC; c++) {
            cudaEventCreateWithFlags(&evG1[c], cudaEventDisableTiming);
            cudaEventCreateWithFlags(&evL1[c], cudaEventDisableTiming);
            cudaEventCreateWithFlags(&evG2[c], cudaEventDisableTiming);
            cudaEventCreateWithFlags(&evL2[c], cudaEventDisableTiming);
            cudaEventCreateWithFlags(&evG3[c], cudaEventDisableTiming);
        }
    }
};
static SideStreams g_ss;

// ---------------- launch: 3-stream, t-chunk pipelined -----------------------------
extern "C" void kernel_launch(void* const* d_in, const int* in_sizes, int n_in,
                              void* d_out, int out_size)
{
    const float* spike = (const float*)d_in[0];
    const float* v1 = (const float*)d_in[1];
    const float* g1 = (const float*)d_in[2];
    const float* v2 = (const float*)d_in[3];
    const float* g2 = (const float*)d_in[4];
    const float* v3 = (const float*)d_in[5];
    const float* g3 = (const float*)d_in[6];
    const float* cds = (const float*)d_in[7];
    const float* vds = (const float*)d_in[8];
    float* out = (float*)d_out;
    cudaStream_t s1 = g_ss.s1, s2 = g_ss.s2;

    // fork
    cudaEventRecord(g_ss.evRoot, 0);
    cudaStreamWaitEvent(s1, g_ss.evRoot, 0);
    cudaStreamWaitEvent(s2, g_ss.evRoot, 0);

    prep_all<<<1616, 256, 0, s2>>>(v1, g1, v2, g2, v3, g3);
    cudaEventRecord(g_ss.evPrep, s2);
    bitpack<<<4096, 256, 0, s1>>>(spike);
    cudaEventRecord(g_ss.evBits, s1);

    // main: three g1 chunks, serial
    cudaStreamWaitEvent(0, g_ss.evPrep, 0);
    cudaStreamWaitEvent(0, g_ss.evBits, 0);

    // -- chunk 0 --
    gather_hid1<<<dim3(CH, B, 2), 128>>>(0);
    cudaEventRecord(g_ss.evG1[0], 0);
    cudaStreamWaitEvent(s1, g_ss.evG1[0], 0);
    lif_hid1<<<(B * CHID) / 128, 128, 0, s1>>>(cds, vds, 0, CH);
    cudaEventRecord(g_ss.evL1[0], s1);

    // -- chunk 1 --
    gather_hid1<<<dim3(CH, B, 2), 128>>>(CH);
    cudaEventRecord(g_ss.evG1[1], 0);
    cudaStreamWaitEvent(s2, g_ss.evL1[0], 0);
    gather_hid2<<<dim3(CH, B), 128, 0, s2>>>(0);
    cudaEventRecord(g_ss.evG2[0], s2);
    cudaStreamWaitEvent(s1, g_ss.evG1[1], 0);
    lif_hid1<<<(B * CHID) / 128, 128, 0, s1>>>(cds, vds, CH, 2 * CH);
    cudaEventRecord(g_ss.evL1[1], s1);

    // -- chunk 2 --
    gather_hid1<<<dim3(CH, B, 2), 128>>>(2 * CH);
    cudaEventRecord(g_ss.evG1[2], 0);
    cudaStreamWaitEvent(s2, g_ss.evL1[1], 0);
    gather_hid2<<<dim3(CH, B), 128, 0, s2>>>(CH);
    cudaEventRecord(g_ss.evG2[1], s2);
    cudaStreamWaitEvent(s1, g_ss.evG2[0], 0);
    lif_hid2<<<(B * CHID) / 128, 128, 0, s1>>>(cds, vds, 0, CH);
    cudaEventRecord(g_ss.evL2[0], s1);
    cudaStreamWaitEvent(s1, g_ss.evG1[2], 0);
    lif_hid1<<<(B * CHID) / 128, 128, 0, s1>>>(cds, vds, 2 * CH, T);
    cudaEventRecord(g_ss.evL1[2], s1);

    // -- tail pipeline --
    cudaStreamWaitEvent(s2, g_ss.evL2[0], 0);
    gather_out<<<dim3(CH, B), 128, 0, s2>>>(0);
    cudaEventRecord(g_ss.evG3[0], s2);
    cudaStreamWaitEvent(s2, g_ss.evL1[2], 0);
    gather_hid2<<<dim3(CH, B), 128, 0, s2>>>(2 * CH);
    cudaEventRecord(g_ss.evG2[2], s2);

    cudaStreamWaitEvent(s1, g_ss.evG2[1], 0);
    lif_hid2<<<(B * CHID) / 128, 128, 0, s1>>>(cds, vds, CH, 2 * CH);
    cudaEventRecord(g_ss.evL2[1], s1);

    cudaStreamWaitEvent(s2, g_ss.evL2[1], 0);
    gather_out<<<dim3(CH, B), 128, 0, s2>>>(CH);
    cudaEventRecord(g_ss.evG3[1], s2);

    cudaStreamWaitEvent(s1, g_ss.evG2[2], 0);
    lif_hid2<<<(B * CHID) / 128, 128, 0, s1>>>(cds, vds, 2 * CH, T);
    cudaEventRecord(g_ss.evL2[2], s1);

    cudaStreamWaitEvent(s2, g_ss.evL2[2], 0);
    gather_out<<<dim3(CH, B), 128, 0, s2>>>(2 * CH);
    cudaEventRecord(g_ss.evG3[2], s2);

    // lif_out after all g3 chunks (s2 serial => evG3[2] implies all)
    cudaStreamWaitEvent(s1, g_ss.evG3[2], 0);
    lif_out<<<(B * COUT + 127) / 128, 128, 0, s1>>>(cds, vds, out);
    cudaEventRecord(g_ss.evEnd, s1);

    // join everything back to the capture-origin stream
    cudaStreamWaitEvent(0, g_ss.evEnd, 0);
}

// round 17
// speedup vs baseline: 1.0581x; 1.0581x over previous
#include <cuda_runtime.h>
#include <cstdint>

#define THRESH 1.25f

constexpr int B    = 16;
constexpr int CIN  = 8192;   // 64*64*2
constexpr int CHID = 512;
constexpr int COUT = 100;
constexpr int T    = 300;
constexpr int NW0  = CIN / 32;   // 256 words per (b,t)
constexpr int NW1  = CHID / 32;  // 16 words per (b,t)
constexpr int HW   = NW0 / 2;    // 128 words per half (layer 1)
constexpr int D    = 10;         // LIF chunk size (T = 30*D)

// ---------------- scratch (static device globals; allocation-free) -------------
__device__ __align__(256) float    d_WT1[CIN * CHID];     // 16 MB  [i][o] (UNSCALED v1^T)
__device__ __align__(256) float    d_WT2[CHID * CHID];    // 1 MB   [i][o] (scaled)
__device__ __align__(256) float    d_WT3[CHID * 128];     // 256 KB [i][o pad 128] (scaled)
__device__ __align__(256) float    d_scale1[CHID];
__device__ __align__(256) unsigned d_bits0[T * B * NW0];  // input spikes [t][b][w]
__device__ __align__(256) unsigned d_bits1[T * B * NW1];  // hidden spikes [t][b][w]
__device__ __align__(256) unsigned d_bits2[T * B * NW1];
__device__ __align__(256) float    d_zpart[2][T * B * CHID]; // layer-1 i-half partials
__device__ __align__(256) float    d_z [T * B * CHID];    // layer-2 z [t][b][o]
__device__ __align__(256) float    d_z3[T * B * COUT];

// ---------------- prep_all: every weight-prep task in one kernel ----------------
// [0,64): L2 norm+transpose; [64,80): L3; [80,592): L1 row norms; [592,1616): L1 transpose
__global__ __launch_bounds__(256) void prep_all(const float* __restrict__ v1,
                                                const float* __restrict__ g1,
                                                const float* __restrict__ v2,
                                                const float* __restrict__ g2,
                                                const float* __restrict__ v3,
                                                const float* __restrict__ g3)
{
    int blk = blockIdx.x;
    int tid = threadIdx.x, lane = tid & 31, w = tid >> 5;

    if (blk >= 592) {
        __shared__ float tile[64][65];
        int idx = blk - 592;
        int i0 = (idx & 127) * 64;
        int o0 = (idx >> 7) * 64;
        int oy = tid >> 4;
        int ix = (tid & 15) * 4;
        #pragma unroll
        for (int k = 0; k < 4; k++) {
            int ol = oy + k * 16;
            float4 val = *(const float4*)&v1[(size_t)(o0 + ol) * CIN + i0 + ix];
            tile[ix + 0][ol] = val.x;
            tile[ix + 1][ol] = val.y;
            tile[ix + 2][ol] = val.z;
            tile[ix + 3][ol] = val.w;
        }
        __syncthreads();
        int iy = tid >> 4;
        int ox = (tid & 15) * 4;
        #pragma unroll
        for (int k = 0; k < 4; k++) {
            int il = iy + k * 16;
            float4 w4;
            w4.x = tile[il][ox + 0];
            w4.y = tile[il][ox + 1];
            w4.z = tile[il][ox + 2];
            w4.w = tile[il][ox + 3];
            *(float4*)&d_WT1[(size_t)(i0 + il) * CHID + o0 + ox] = w4;
        }
        return;
    }

    if (blk >= 80) {
        __shared__ float red[8];
        int r = blk - 80;
        const float* row = v1 + (size_t)r * CIN;
        float s = 0.f;
        for (int i = tid; i < CIN; i += 256) { float x = row[i]; s = fmaf(x, x, s); }
        #pragma unroll
        for (int d = 16; d > 0; d >>= 1) s += __shfl_down_sync(0xffffffffu, s, d);
        if (lane == 0) red[w] = s;
        __syncthreads();
        if (tid == 0) {
            float tot = 0.f;
            #pragma unroll
            for (int j = 0; j < 8; j++) tot += red[j];
            d_scale1[r] = g1[r] / sqrtf(tot);
        }
        return;
    }

    const float *v, *g;
    float* wt;
    int bx, by, OSTRIDE, NOV;
    if (blk < 64) { v = v2; g = g2; wt = d_WT2; bx = blk & 7; by = blk >> 3; OSTRIDE = 512; NOV = 512; }
    else { int l = blk - 64; v = v3; g = g3; wt = d_WT3; bx = l & 7; by = l >> 3; OSTRIDE = 128; NOV = 100; }
    constexpr int NI = 512;
    int i0 = bx * 64, o0 = by * 64;

    __shared__ float sscale[64];
    __shared__ float tile[64][65];

    #pragma unroll
    for (int r = 0; r < 8; r++) {
        int o = o0 + w * 8 + r;
        float s = 0.f;
        if (o < NOV) {
            const float* row = v + (size_t)o * NI;
            #pragma unroll
            for (int k = 0; k < 16; k++) { float x = row[lane + 32 * k]; s = fmaf(x, x, s); }
        }
        #pragma unroll
        for (int d = 16; d > 0; d >>= 1) s += __shfl_down_sync(0xffffffffu, s, d);
        if (lane == 0) sscale[w * 8 + r] = (o < NOV) ? g[o] / sqrtf(s) : 0.f;
    }
    __syncthreads();

    int oy = tid >> 4;
    int ix = (tid & 15) * 4;
    #pragma unroll
    for (int k = 0; k < 4; k++) {
        int ol = oy + k * 16;
        int o  = o0 + ol;
        float4 val = make_float4(0.f, 0.f, 0.f, 0.f);
        if (o < NOV) val = *(const float4*)&v[(size_t)o * NI + i0 + ix];
        tile[ix + 0][ol] = val.x;
        tile[ix + 1][ol] = val.y;
        tile[ix + 2][ol] = val.z;
        tile[ix + 3][ol] = val.w;
    }
    __syncthreads();

    int iy = tid >> 4;
    int ox = (tid & 15) * 4;
    float4 sc;
    sc.x = sscale[ox + 0]; sc.y = sscale[ox + 1];
    sc.z = sscale[ox + 2]; sc.w = sscale[ox + 3];
    #pragma unroll
    for (int k = 0; k < 4; k++) {
        int il = iy + k * 16;
        float4 w4;
        w4.x = tile[il][ox + 0] * sc.x;
        w4.y = tile[il][ox + 1] * sc.y;
        w4.z = tile[il][ox + 2] * sc.z;
        w4.w = tile[il][ox + 3] * sc.w;
        *(float4*)&wt[(size_t)(i0 + il) * OSTRIDE + o0 + ox] = w4;
    }
}

// ---------------- bitpack (coalesced, smem byte-transpose) ----------------------
__global__ __launch_bounds__(256) void bitpack(const float* __restrict__ spike)
{
    __shared__ unsigned char sb[32 * 308];
    int blk = blockIdx.x;
    int b  = blk >> 8;
    int ig = blk & 255;
    int tid = threadIdx.x, lane = tid & 31, w = tid >> 5;

    #pragma unroll
    for (int k = 0; k < 4; k++) {
        int il = w + 8 * k;
        const float4* row4 = (const float4*)(spike + ((size_t)b * CIN + ig * 32 + il) * T);
        #pragma unroll
        for (int j = 0; j < 3; j++) {
            int f = lane + 32 * j;
            if (f < 75) {
                float4 v = row4[f];
                unsigned p = (v.x > 0.5f ? 1u : 0u)
                           | (v.y > 0.5f ? 1u : 0u) << 8
                           | (v.z > 0.5f ? 1u : 0u) << 16
                           | (v.w > 0.5f ? 1u : 0u) << 24;
                *(unsigned*)&sb[il * 308 + 4 * f] = p;
            }
        }
    }
    __syncthreads();
    for (int t = tid; t < T; t += 256) {
        unsigned m = 0;
        #pragma unroll
        for (int i = 0; i < 32; i++) m |= (unsigned)sb[i * 308 + t] << i;
        d_bits0[(size_t)t * (B * NW0) + b * NW0 + ig] = m;
    }
}

// ---------------- layer-1 sparse gather, i-halved, float4 x 128 ----------------
__global__ __launch_bounds__(128) void gather_hid1()
{
    const float4* __restrict__ wt = (const float4*)d_WT1;
    int t = blockIdx.x, b = blockIdx.y, h = blockIdx.z;
    const unsigned* bp = d_bits0 + ((size_t)t * B + b) * NW0 + h * HW;

    __shared__ unsigned short sidx[HW * 32];
    __shared__ int wcnt[4];
    int tid = threadIdx.x, lane = tid & 31, w = tid >> 5;

    int word = w * 32 + lane;
    unsigned m = bp[word];
    int c = __popc(m);
    int x = c;
    #pragma unroll
    for (int d = 1; d < 32; d <<= 1) {
        int y = __shfl_up_sync(0xffffffffu, x, d);
        if (lane >= d) x += y;
    }
    if (lane == 31) wcnt[w] = x;
    __syncthreads();
    int base = 0;
    #pragma unroll
    for (int j = 0; j < 4; j++) if (j < w) base += wcnt[j];
    int mybase = base + x - c;
    while (m) {
        int bpos = __ffs((int)m) - 1;
        m &= m - 1;
        sidx[mybase++] = (unsigned short)(word * 32 + bpos);
    }
    __syncthreads();

    int cnt = wcnt[0] + wcnt[1] + wcnt[2] + wcnt[3];
    int rowbase = h * (CIN / 2);

    float ax = 0.f, ay = 0.f, az = 0.f, aw = 0.f;
    int k = 0;
    for (; k + 8 <= cnt; k += 8) {
        float4 r[8];
        #pragma unroll
        for (int u = 0; u < 8; u++) {
            int i = rowbase + sidx[k + u];
            r[u] = wt[(size_t)i * 128 + tid];
        }
        #pragma unroll
        for (int u = 0; u < 8; u++) { ax += r[u].x; ay += r[u].y; az += r[u].z; aw += r[u].w; }
    }
    for (; k < cnt; k++) {
        int i = rowbase + sidx[k];
        float4 r0 = wt[(size_t)i * 128 + tid];
        ax += r0.x; ay += r0.y; az += r0.z; aw += r0.w;
    }
    float4 o; o.x = ax; o.y = ay; o.z = az; o.w = aw;
    ((float4*)d_zpart[h])[((size_t)t * B + b) * 128 + tid] = o;
}

// ---------------- LIF layer 1: batched double-buffered loads --------------------
// chunk of D=10 steps: load next chunk into bufB (one load batch), compute from
// bufA (covers the L2 wait), copy B->A (static reg moves). No rolling prefetch.
__global__ __launch_bounds__(128) void lif_hid1(const float* __restrict__ cds,
                                                const float* __restrict__ vds)
{
    int gid  = blockIdx.x * blockDim.x + threadIdx.x;  // b*512+o
    int lane = threadIdx.x & 31;
    float a  = 1.f - cds[0];
    float bb = 1.f - vds[0];
    float sc = d_scale1[gid & (CHID - 1)];
    float cur = 0.f, volt = 0.f;

    float2 bufA[D], bufB[D];
    #pragma unroll
    for (int j = 0; j < D; j++) {
        bufA[j].x = d_zpart[0][(size_t)j * (B * CHID) + gid];
        bufA[j].y = d_zpart[1][(size_t)j * (B * CHID) + gid];
    }

    for (int c = 0; c < T / D; c++) {
        int tn = (c + 1) * D;
        if (tn < T) {
            #pragma unroll
            for (int j = 0; j < D; j++) {
                bufB[j].x = d_zpart[0][(size_t)(tn + j) * (B * CHID) + gid];
                bufB[j].y = d_zpart[1][(size_t)(tn + j) * (B * CHID) + gid];
            }
        }
        int t0 = c * D;
        #pragma unroll
        for (int j = 0; j < D; j++) {
            int t = t0 + j;
            float zt = (bufA[j].x + bufA[j].y) * sc;
            cur  = fmaf(a, cur, zt);
            volt = fmaf(bb, volt, cur);
            bool s = volt >= THRESH;
            unsigned msk = __ballot_sync(0xffffffffu, s);
            volt = s ? 0.f : volt;
            if (lane == 0) d_bits1[(size_t)t * (B * NW1) + (gid >> 5)] = msk;
        }
        #pragma unroll
        for (int j = 0; j < D; j++) bufA[j] = bufB[j];
    }
}

// ---------------- layer-2 sparse gather, per-t full-width, float4 x 128 --------
__global__ __launch_bounds__(128) void gather_hid2()
{
    const float4* __restrict__ wt = (const float4*)d_WT2;
    int t = blockIdx.x, b = blockIdx.y;
    const unsigned* bp = d_bits1 + ((size_t)t * B + b) * NW1;

    __shared__ unsigned short sidx[NW1 * 32];
    __shared__ int scount;
    int tid = threadIdx.x, lane = tid & 31;

    if (tid < 32) {
        unsigned m = (lane < NW1) ? bp[lane] : 0u;
        int c = __popc(m);
        int x = c;
        #pragma unroll
        for (int d = 1; d < 32; d <<= 1) {
            int y = __shfl_up_sync(0xffffffffu, x, d);
            if (lane >= d) x += y;
        }
        int base = x - c;
        while (m) {
            int bpos = __ffs((int)m) - 1;
            m &= m - 1;
            sidx[base++] = (unsigned short)(lane * 32 + bpos);
        }
        if (lane == 31) scount = x;
    }
    __syncthreads();

    int cnt = scount;
    float ax = 0.f, ay = 0.f, az = 0.f, aw = 0.f;
    int k = 0;
    for (; k + 8 <= cnt; k += 8) {
        float4 r[8];
        #pragma unroll
        for (int u = 0; u < 8; u++) { int i = sidx[k + u]; r[u] = wt[(size_t)i * 128 + tid]; }
        #pragma unroll
        for (int u = 0; u < 8; u++) { ax += r[u].x; ay += r[u].y; az += r[u].z; aw += r[u].w; }
    }
    for (; k < cnt; k++) {
        float4 r0 = wt[(size_t)sidx[k] * 128 + tid];
        ax += r0.x; ay += r0.y; az += r0.z; aw += r0.w;
    }
    float4 o; o.x = ax; o.y = ay; o.z = az; o.w = aw;
    ((float4*)d_z)[((size_t)t * B + b) * 128 + tid] = o;
}

// ---------------- LIF layer 2: batched double-buffered loads --------------------
__global__ __launch_bounds__(128) void lif_hid2(const float* __restrict__ cds,
                                                const float* __restrict__ vds)
{
    int gid  = blockIdx.x * blockDim.x + threadIdx.x;
    int lane = threadIdx.x & 31;
    float a  = 1.f - cds[1];
    float bb = 1.f - vds[1];
    float cur = 0.f, volt = 0.f;

    float bufA[D], bufB[D];
    #pragma unroll
    for (int j = 0; j < D; j++) bufA[j] = d_z[(size_t)j * (B * CHID) + gid];

    for (int c = 0; c < T / D; c++) {
        int tn = (c + 1) * D;
        if (tn < T) {
            #pragma unroll
            for (int j = 0; j < D; j++) bufB[j] = d_z[(size_t)(tn + j) * (B * CHID) + gid];
        }
        int t0 = c * D;
        #pragma unroll
        for (int j = 0; j < D; j++) {
            int t = t0 + j;
            float zt = bufA[j];
            cur  = fmaf(a, cur, zt);
            volt = fmaf(bb, volt, cur);
            bool s = volt >= THRESH;
            unsigned msk = __ballot_sync(0xffffffffu, s);
            volt = s ? 0.f : volt;
            if (lane == 0) d_bits2[(size_t)t * (B * NW1) + (gid >> 5)] = msk;
        }
        #pragma unroll
        for (int j = 0; j < D; j++) bufA[j] = bufB[j];
    }
}

// ---------------- layer-3 per-t gather ------------------------------------------
__global__ void gather_out()
{
    int t = blockIdx.x, b = blockIdx.y;
    const unsigned* bp = d_bits2 + ((size_t)t * B + b) * NW1;

    __shared__ unsigned short sidx[NW1 * 32];
    __shared__ int scount;
    int tid = threadIdx.x, lane = tid & 31;

    if (tid < 32) {
        unsigned m = (lane < NW1) ? bp[lane] : 0u;
        int c = __popc(m);
        int x = c;
        #pragma unroll
        for (int d = 1; d < 32; d <<= 1) {
            int y = __shfl_up_sync(0xffffffffu, x, d);
            if (lane >= d) x += y;
        }
        int base = x - c;
        while (m) {
            int bpos = __ffs((int)m) - 1;
            m &= m - 1;
            sidx[base++] = (unsigned short)(lane * 32 + bpos);
        }
        if (lane == 31) scount = x;
    }
    __syncthreads();

    int cnt = scount;
    float acc = 0.f;
    int k = 0;
    for (; k + 8 <= cnt; k += 8) {
        float r[8];
        #pragma unroll
        for (int u = 0; u < 8; u++) { int i = sidx[k + u]; r[u] = d_WT3[i * 128 + tid]; }
        #pragma unroll
        for (int u = 0; u < 8; u++) acc += r[u];
    }
    for (; k < cnt; k++) acc += d_WT3[sidx[k] * 128 + tid];

    if (tid < COUT) d_z3[((size_t)t * B + b) * COUT + tid] = acc;
}

// ---------------- LIF output layer: batched double-buffered loads ----------------
__global__ __launch_bounds__(128) void lif_out(const float* __restrict__ cds,
                                               const float* __restrict__ vds,
                                               float* __restrict__ out)
{
    int gid = blockIdx.x * blockDim.x + threadIdx.x;
    if (gid >= B * COUT) return;
    int b = gid / COUT, c = gid % COUT;
    float a  = 1.f - cds[2];
    float bb = 1.f - vds[2];
    float cur = 0.f, volt = 0.f;
    float* orow = out + ((size_t)b * COUT + c) * T;

    float bufA[D], bufB[D];
    #pragma unroll
    for (int j = 0; j < D; j++) bufA[j] = d_z3[(size_t)j * (B * COUT) + gid];

    for (int ch = 0; ch < T / D; ch++) {
        int tn = (ch + 1) * D;
        if (tn < T) {
            #pragma unroll
            for (int j = 0; j < D; j++) bufB[j] = d_z3[(size_t)(tn + j) * (B * COUT) + gid];
        }
        int t0 = ch * D;
        #pragma unroll
        for (int j = 0; j < D; j++) {
            int t = t0 + j;
            float zt = bufA[j];
            cur  = fmaf(a, cur, zt);
            volt = fmaf(bb, volt, cur);
            bool s = volt >= THRESH;
            volt = s ? 0.f : volt;
            orow[t] = s ? 1.0f : 0.0f;
        }
        #pragma unroll
        for (int j = 0; j < D; j++) bufA[j] = bufB[j];
    }
}

// ---------------- streams/events (context resources, not tracked device mem) ---
struct SideStreams {
    cudaStream_t s1, s2;
    cudaEvent_t  evRoot, evBits, evPrep;
    SideStreams() {
        cudaStreamCreateWithFlags(&s1, cudaStreamNonBlocking);
        cudaStreamCreateWithFlags(&s2, cudaStreamNonBlocking);
        cudaEventCreateWithFlags(&evRoot, cudaEventDisableTiming);
        cudaEventCreateWithFlags(&evBits, cudaEventDisableTiming);
        cudaEventCreateWithFlags(&evPrep, cudaEventDisableTiming);
    }
};
static SideStreams g_ss;

// ---------------- launch ---------------------------------------------------------
extern "C" void kernel_launch(void* const* d_in, const int* in_sizes, int n_in,
                              void* d_out, int out_size)
{
    const float* spike = (const float*)d_in[0];
    const float* v1 = (const float*)d_in[1];
    const float* g1 = (const float*)d_in[2];
    const float* v2 = (const float*)d_in[3];
    const float* g2 = (const float*)d_in[4];
    const float* v3 = (const float*)d_in[5];
    const float* g3 = (const float*)d_in[6];
    const float* cds = (const float*)d_in[7];
    const float* vds = (const float*)d_in[8];
    float* out = (float*)d_out;

    // fork
    cudaEventRecord(g_ss.evRoot, 0);
    cudaStreamWaitEvent(g_ss.s1, g_ss.evRoot, 0);
    cudaStreamWaitEvent(g_ss.s2, g_ss.evRoot, 0);

    // #1: ALL weight prep on s2 (incl. unscaled L1 transpose; scale applied in lif1)
    prep_all<<<1616, 256, 0, g_ss.s2>>>(v1, g1, v2, g2, v3, g3);
    cudaEventRecord(g_ss.evPrep, g_ss.s2);

    // #2: pure bitpack on s1 (fully parallel with prep_all)
    bitpack<<<4096, 256, 0, g_ss.s1>>>(spike);
    cudaEventRecord(g_ss.evBits, g_ss.s1);

    // main chain (serial; R12 structure)
    cudaStreamWaitEvent(0, g_ss.evPrep, 0);
    cudaStreamWaitEvent(0, g_ss.evBits, 0);
    gather_hid1<<<dim3(T, B, 2), 128>>>();                   // #3
    lif_hid1<<<(B * CHID) / 128, 128>>>(cds, vds);           // #4 (profiled)
    gather_hid2<<<dim3(T, B), 128>>>();                      // #5
    lif_hid2<<<(B * CHID) / 128, 128>>>(cds, vds);           // #6
    gather_out<<<dim3(T, B), 128>>>();                       // #7
    lif_out<<<(B * COUT + 127) / 128, 128>>>(cds, vds, out); // #8
}